// round 1
// baseline (speedup 1.0000x reference)
#include <cuda_runtime.h>

#define TT 512
#define BB 64
#define II 1024
#define HH 1024
#define NB 128   // persistent CTAs for the recurrence (<=148 -> all resident)

// h3 exchange buffer, transposed [parity][k][b] so phase-B loads are coalesced float4s
__device__ float g_h3[2][HH][BB];
__device__ unsigned int g_cnt;
__device__ volatile unsigned int g_flag;

__global__ void init_sync_kernel() { g_cnt = 0; g_flag = 0; }

__device__ __forceinline__ unsigned long long pk2(float lo, float hi) {
    unsigned long long r;
    asm("mov.b64 %0, {%1, %2};" : "=l"(r) : "f"(lo), "f"(hi));
    return r;
}
__device__ __forceinline__ unsigned long long ffma2(unsigned long long a,
                                                    unsigned long long b,
                                                    unsigned long long c) {
    unsigned long long d;
    asm("fma.rn.f32x2 %0, %1, %2, %3;" : "=l"(d) : "l"(a), "l"(b), "l"(c));
    return d;
}
__device__ __forceinline__ float psum(unsigned long long p) {
    float lo = __uint_as_float((unsigned int)(p & 0xFFFFFFFFull));
    float hi = __uint_as_float((unsigned int)(p >> 32));
    return lo + hi;
}
__device__ __forceinline__ void st_pair4(float* p, float4 v) {
    *(unsigned long long*)(p)     = pk2(v.x, v.y);
    *(unsigned long long*)(p + 2) = pk2(v.z, v.w);
}

// ---------------------------------------------------------------------------
// xw = x @ W^T + bW   (M=B*T=32768, N=1024, K=1024), written into d_out(out1)
// BM=128, BN=128, BK=16, 256 threads, 8x8 thread tile, f32x2 paired over k.
// smem pitch 18 floats (72B = 9*8B, odd in 8B units -> conflict-free LDS.64).
// ---------------------------------------------------------------------------
__global__ __launch_bounds__(256, 1)
void gemm_xw_kernel(const float* __restrict__ X, const float* __restrict__ W,
                    const float* __restrict__ bW, float* __restrict__ C) {
    __shared__ float xs[128][18];
    __shared__ float ws[128][18];

    const int tid = threadIdx.x;
    const int m0 = blockIdx.y * 128;
    const int n0 = blockIdx.x * 128;
    const int tm = tid & 15;   // m = m0 + tm + 16*i  (lanes 0..15 contiguous tm)
    const int tn = tid >> 4;   // n = n0 + tn + 16*j  (uniform per half-warp -> broadcast)
    const int lr = tid >> 2;         // loader row 0..63 (+64)
    const int lc = (tid & 3) << 2;   // loader col {0,4,8,12}

    const float* xg = X + (size_t)(m0 + lr) * II + lc;
    const float* wg = W + (size_t)(n0 + lr) * II + lc;

    unsigned long long acc[8][8];
#pragma unroll
    for (int i = 0; i < 8; i++)
#pragma unroll
        for (int j = 0; j < 8; j++) acc[i][j] = 0ull;

    float4 xa = *(const float4*)(xg);
    float4 xb = *(const float4*)(xg + 64 * II);
    float4 wa = *(const float4*)(wg);
    float4 wb = *(const float4*)(wg + 64 * II);

    for (int k0 = 0; k0 < II; k0 += 16) {
        __syncthreads();
        st_pair4(&xs[lr][lc], xa);
        st_pair4(&xs[lr + 64][lc], xb);
        st_pair4(&ws[lr][lc], wa);
        st_pair4(&ws[lr + 64][lc], wb);
        __syncthreads();
        if (k0 + 16 < II) {   // prefetch next tile while computing this one
            xa = *(const float4*)(xg + k0 + 16);
            xb = *(const float4*)(xg + 64 * II + k0 + 16);
            wa = *(const float4*)(wg + k0 + 16);
            wb = *(const float4*)(wg + 64 * II + k0 + 16);
        }
#pragma unroll
        for (int kp = 0; kp < 8; kp++) {
            unsigned long long af[8], bf[8];
#pragma unroll
            for (int i = 0; i < 8; i++)
                af[i] = *(const unsigned long long*)&xs[tm + 16 * i][kp * 2];
#pragma unroll
            for (int j = 0; j < 8; j++)
                bf[j] = *(const unsigned long long*)&ws[tn + 16 * j][kp * 2];
#pragma unroll
            for (int i = 0; i < 8; i++)
#pragma unroll
                for (int j = 0; j < 8; j++)
                    acc[i][j] = ffma2(af[i], bf[j], acc[i][j]);
        }
    }

#pragma unroll
    for (int i = 0; i < 8; i++) {
        const int m = m0 + tm + 16 * i;
#pragma unroll
        for (int j = 0; j < 8; j++) {
            const int n = n0 + tn + 16 * j;
            C[(size_t)m * HH + n] = psum(acc[i][j]) + bW[n];
        }
    }
}

// ---------------------------------------------------------------------------
// Persistent recurrence kernel. 128 CTAs x 256 thr; CTA owns 8 H-columns,
// its U slice (8x1024 f32 = 32KB) lives in smem for all 512 steps.
// Per step: phase A (tanh + write h3 + out1), grid barrier, phase B
// (warp-split-k 64x1024x1024 partial GEMM with f32x2, smem reduction).
// ---------------------------------------------------------------------------
__global__ __launch_bounds__(256, 1)
void rnn_steps_kernel(const float* __restrict__ U, const float* __restrict__ bU,
                      float* __restrict__ out) {
    extern __shared__ float smem[];
    float (*Usm)[1024] = (float (*)[1024])smem;            // 8*1024 = 32KB
    float (*red)[512]  = (float (*)[512])(smem + 8 * 1024); // 8*512  = 16KB

    const int tid = threadIdx.x;
    const int c0 = blockIdx.x * 8;

    // load this CTA's U slice (rows c0..c0+7), coalesced
    for (int idx = tid; idx < 8 * 1024; idx += 256) {
        const int r = idx >> 10, k = idx & 1023;
        Usm[r][k] = U[(size_t)(c0 + r) * HH + k];
    }

    // this thread's 2 outputs: o = tid*2 + {0,1} -> (b_o, c_o), (b_o, c_o+1)
    const int o0 = tid * 2;
    const int b_o = o0 >> 3;
    const int c_o = o0 & 7;
    const float bu0 = bU[c0 + c_o];
    const float bu1 = bU[c0 + c_o + 1];
    float st0 = 0.f, st1 = 0.f;

    // phase-B decomposition: warp w owns k in [w*128, w*128+128)
    const int w    = tid >> 5;
    const int lane = tid & 31;
    const int bg   = lane & 15;  // b = bg*4 + i, lanes 0..15 contiguous -> coalesced
    const int cg   = lane >> 4;  // c_local = cg*4 + q (uniform per half -> U broadcast)
    const int kbase = w * 128;

    __syncthreads();

    for (int t = 0; t < TT; t++) {
        const int par = t & 1;
        // ---- phase A: h3 = tanh(xw_t + state); out1 overwritten in place ----
        {
            const size_t idx0 = ((size_t)b_o * TT + t) * HH + c0 + c_o;
            const float h0 = tanhf(out[idx0]     + st0);
            const float h1 = tanhf(out[idx0 + 1] + st1);
            out[idx0]     = h0;
            out[idx0 + 1] = h1;
            g_h3[par][c0 + c_o][b_o]     = h0;
            g_h3[par][c0 + c_o + 1][b_o] = h1;
            if (t == TT - 1) {
                const size_t o2 = (size_t)BB * TT * HH + (size_t)b_o * HH + c0 + c_o;
                out[o2]     = h0;
                out[o2 + 1] = h1;
            }
        }
        if (t == TT - 1) break;   // no more state needed

        // ---- grid barrier (sense via monotone phase; reset each launch) ----
        __threadfence();
        __syncthreads();
        if (tid == 0) {
            const unsigned int target = (unsigned int)(t + 1);
            if (atomicAdd(&g_cnt, 1) == NB - 1) {
                g_cnt = 0;
                __threadfence();
                g_flag = target;
            } else {
                while (g_flag < target) { }
            }
        }
        __syncthreads();

        // ---- phase B: state' = h3 @ U_slice^T (warp-split over k) ----
        unsigned long long acc[4][4];
#pragma unroll
        for (int i = 0; i < 4; i++)
#pragma unroll
            for (int q = 0; q < 4; q++) acc[i][q] = 0ull;

        const float* h3base = &g_h3[par][0][0];
#pragma unroll 4
        for (int kp = 0; kp < 64; kp++) {
            const int k0 = kbase + kp * 2;
            const float4 v0 = __ldcg((const float4*)(h3base + (size_t)k0 * BB + bg * 4));
            const float4 v1 = __ldcg((const float4*)(h3base + (size_t)(k0 + 1) * BB + bg * 4));
            const unsigned long long a0 = pk2(v0.x, v1.x);
            const unsigned long long a1 = pk2(v0.y, v1.y);
            const unsigned long long a2 = pk2(v0.z, v1.z);
            const unsigned long long a3 = pk2(v0.w, v1.w);
#pragma unroll
            for (int q = 0; q < 4; q++) {
                const unsigned long long u =
                    *(const unsigned long long*)&Usm[cg * 4 + q][k0];
                acc[0][q] = ffma2(a0, u, acc[0][q]);
                acc[1][q] = ffma2(a1, u, acc[1][q]);
                acc[2][q] = ffma2(a2, u, acc[2][q]);
                acc[3][q] = ffma2(a3, u, acc[3][q]);
            }
        }
        // write warp partials, then 8-way cross-warp sum per output
#pragma unroll
        for (int i = 0; i < 4; i++) {
            const int b = bg * 4 + i;
#pragma unroll
            for (int q = 0; q < 4; q++) {
                red[w][b * 8 + cg * 4 + q] = psum(acc[i][q]);
            }
        }
        __syncthreads();
        float s0 = bu0, s1 = bu1;
#pragma unroll
        for (int ww = 0; ww < 8; ww++) {
            s0 += red[ww][o0];
            s1 += red[ww][o0 + 1];
        }
        st0 = s0;
        st1 = s1;
        // red reuse next step is protected by the barrier's __syncthreads()
    }
}

extern "C" void kernel_launch(void* const* d_in, const int* in_sizes, int n_in,
                              void* d_out, int out_size) {
    const float* x  = (const float*)d_in[0];
    const float* W  = (const float*)d_in[1];
    const float* bW = (const float*)d_in[2];
    const float* U  = (const float*)d_in[3];
    const float* bU = (const float*)d_in[4];
    float* out = (float*)d_out;

    init_sync_kernel<<<1, 1>>>();

    dim3 ggrid(HH / 128, (BB * TT) / 128);  // (8, 256)
    gemm_xw_kernel<<<ggrid, 256>>>(x, W, bW, out);

    rnn_steps_kernel<<<NB, 256, (8 * 1024 + 8 * 512) * sizeof(float)>>>(U, bU, out);
}

// round 2
// speedup vs baseline: 1.0491x; 1.0491x over previous
#include <cuda_runtime.h>

#define TT 512
#define BB 64
#define II 1024
#define HH 1024
#define NB 128       // persistent CTAs (<=148 -> all resident, barrier safe)
#define UPITCH 1026  // padded smem pitch for U slice

// h3 exchange buffer, [parity][h-index][b] so phase-B loads are coalesced float4
__device__ float g_h3[2][HH][BB];
__device__ unsigned int g_cnt;
__device__ volatile unsigned int g_flag;

__device__ __forceinline__ unsigned long long pk2(float lo, float hi) {
    unsigned long long r;
    asm("mov.b64 %0, {%1, %2};" : "=l"(r) : "f"(lo), "f"(hi));
    return r;
}
__device__ __forceinline__ unsigned long long ffma2(unsigned long long a,
                                                    unsigned long long b,
                                                    unsigned long long c) {
    unsigned long long d;
    asm("fma.rn.f32x2 %0, %1, %2, %3;" : "=l"(d) : "l"(a), "l"(b), "l"(c));
    return d;
}
__device__ __forceinline__ float psum(unsigned long long p) {
    float lo = __uint_as_float((unsigned int)(p & 0xFFFFFFFFull));
    float hi = __uint_as_float((unsigned int)(p >> 32));
    return lo + hi;
}
__device__ __forceinline__ void st_pair4(float* p, float4 v) {
    *(unsigned long long*)(p)     = pk2(v.x, v.y);
    *(unsigned long long*)(p + 2) = pk2(v.z, v.w);
}

// ---------------------------------------------------------------------------
// xw = x @ W^T + bW   (M=32768, N=1024, K=1024) -> d_out (out1 region)
// BM=BN=128, BK=16, 256 threads, 8x8 tile, f32x2-paired over k.
// Block (0,0) also resets the grid-barrier state for the following kernel.
// ---------------------------------------------------------------------------
__global__ __launch_bounds__(256, 1)
void gemm_xw_kernel(const float* __restrict__ X, const float* __restrict__ W,
                    const float* __restrict__ bW, float* __restrict__ C) {
    if (blockIdx.x == 0 && blockIdx.y == 0 && threadIdx.x == 0) {
        g_cnt = 0;
        g_flag = 0;
    }

    __shared__ float xs[128][18];
    __shared__ float ws[128][18];

    const int tid = threadIdx.x;
    const int m0 = blockIdx.y * 128;
    const int n0 = blockIdx.x * 128;
    const int tm = tid & 15;
    const int tn = tid >> 4;
    const int lr = tid >> 2;
    const int lc = (tid & 3) << 2;

    const float* xg = X + (size_t)(m0 + lr) * II + lc;
    const float* wg = W + (size_t)(n0 + lr) * II + lc;

    unsigned long long acc[8][8];
#pragma unroll
    for (int i = 0; i < 8; i++)
#pragma unroll
        for (int j = 0; j < 8; j++) acc[i][j] = 0ull;

    float4 xa = *(const float4*)(xg);
    float4 xb = *(const float4*)(xg + 64 * II);
    float4 wa = *(const float4*)(wg);
    float4 wb = *(const float4*)(wg + 64 * II);

    for (int k0 = 0; k0 < II; k0 += 16) {
        __syncthreads();
        st_pair4(&xs[lr][lc], xa);
        st_pair4(&xs[lr + 64][lc], xb);
        st_pair4(&ws[lr][lc], wa);
        st_pair4(&ws[lr + 64][lc], wb);
        __syncthreads();
        if (k0 + 16 < II) {
            xa = *(const float4*)(xg + k0 + 16);
            xb = *(const float4*)(xg + 64 * II + k0 + 16);
            wa = *(const float4*)(wg + k0 + 16);
            wb = *(const float4*)(wg + 64 * II + k0 + 16);
        }
#pragma unroll
        for (int kp = 0; kp < 8; kp++) {
            unsigned long long af[8], bf[8];
#pragma unroll
            for (int i = 0; i < 8; i++)
                af[i] = *(const unsigned long long*)&xs[tm + 16 * i][kp * 2];
#pragma unroll
            for (int j = 0; j < 8; j++)
                bf[j] = *(const unsigned long long*)&ws[tn + 16 * j][kp * 2];
#pragma unroll
            for (int i = 0; i < 8; i++)
#pragma unroll
                for (int j = 0; j < 8; j++)
                    acc[i][j] = ffma2(af[i], bf[j], acc[i][j]);
        }
    }

#pragma unroll
    for (int i = 0; i < 8; i++) {
        const int m = m0 + tm + 16 * i;
#pragma unroll
        for (int j = 0; j < 8; j++) {
            const int n = n0 + tn + 16 * j;
            C[(size_t)m * HH + n] = psum(acc[i][j]) + bW[n];
        }
    }
}

// ---------------------------------------------------------------------------
// Persistent recurrence. 128 CTAs = 4(b) x 32(c) tiles of 16b x 32c.
// U slice (32x1024) resident in smem all 512 steps. Per step:
//   wait(all h3(t) written) -> tile GEMM s = h3(t) @ Uslice^T (warp split-k,
//   f32x2) -> h3(t+1) = tanh(xw_{t+1} + s) for OWN tile -> write out1/h3 ->
//   fence -> arrive.  State never crosses CTAs; ONE barrier per step.
// ---------------------------------------------------------------------------
__global__ __launch_bounds__(256, 1)
void rnn_steps_kernel(const float* __restrict__ U, const float* __restrict__ bU,
                      float* __restrict__ out) {
    extern __shared__ float smem[];
    float* Usm = smem;                 // 32 * UPITCH floats (~128KB)
    float* red = smem + 32 * UPITCH;   // 8 * 512 floats (16KB)

    const int tid = threadIdx.x;
    const int cgid = blockIdx.x & 31;
    const int bgid = blockIdx.x >> 5;
    const int c0 = cgid * 32;
    const int b0 = bgid * 16;

    // load this CTA's 32 U rows (coalesced)
    for (int idx = tid; idx < 32 * 1024; idx += 256) {
        const int r = idx >> 10, k = idx & 1023;
        Usm[r * UPITCH + k] = U[(size_t)(c0 + r) * HH + k];
    }

    // this thread's 2 outputs within the tile
    const int o0 = 2 * tid;
    const int blo = o0 >> 5;          // 0..15
    const int clo = o0 & 31;          // even
    const int b = b0 + blo;
    const int c = c0 + clo;
    const float bu0 = bU[c];
    const float bu1 = bU[c + 1];

    // phase-B split-k lane mapping
    const int w = tid >> 5;           // warp: k in [w*128, w*128+128)
    const int lane = tid & 31;
    const int bg = lane & 3;          // 4 b-quads (16 b total)
    const int cg = lane >> 2;         // 8 c-quads (32 c total)
    const int kbase = w * 128;
    const int hoff = b0 + bg * 4;

    __syncthreads();

    // t = 0 : h3(0) = tanh(xw_0), no state
    {
        const size_t idx = ((size_t)b * TT) * HH + c;
        const float2 xw = *(const float2*)&out[idx];
        const float h0 = tanhf(xw.x);
        const float h1 = tanhf(xw.y);
        out[idx] = h0;
        out[idx + 1] = h1;
        g_h3[0][c][b] = h0;
        g_h3[0][c + 1][b] = h1;
    }
    __threadfence();
    __syncthreads();
    if (tid == 0) {
        if (atomicAdd(&g_cnt, 1) == NB - 1) {
            g_cnt = 0;
            __threadfence();
            g_flag = 1;
        } else {
            while (g_flag < 1u) { }
        }
    }
    __syncthreads();

    for (int t = 0; t < TT - 1; t++) {
        const int par = t & 1;
        // prefetch next xw for this thread's outputs (hidden under k-loop)
        const size_t nidx = ((size_t)b * TT + (t + 1)) * HH + c;
        const float2 xwn = *(const float2*)&out[nidx];

        unsigned long long acc[4][4];
#pragma unroll
        for (int i = 0; i < 4; i++)
#pragma unroll
            for (int q = 0; q < 4; q++) acc[i][q] = 0ull;

        const float* hb = &g_h3[par][0][0];
#pragma unroll 8
        for (int kp = 0; kp < 64; kp++) {
            const int k0 = kbase + 2 * kp;
            const float4 v0 = __ldcg((const float4*)(hb + (size_t)k0 * BB + hoff));
            const float4 v1 = __ldcg((const float4*)(hb + (size_t)(k0 + 1) * BB + hoff));
            const unsigned long long a0 = pk2(v0.x, v1.x);
            const unsigned long long a1 = pk2(v0.y, v1.y);
            const unsigned long long a2 = pk2(v0.z, v1.z);
            const unsigned long long a3 = pk2(v0.w, v1.w);
#pragma unroll
            for (int q = 0; q < 4; q++) {
                const unsigned long long u =
                    *(const unsigned long long*)&Usm[(cg * 4 + q) * UPITCH + k0];
                acc[0][q] = ffma2(a0, u, acc[0][q]);
                acc[1][q] = ffma2(a1, u, acc[1][q]);
                acc[2][q] = ffma2(a2, u, acc[2][q]);
                acc[3][q] = ffma2(a3, u, acc[3][q]);
            }
        }

        // warp partials -> smem
#pragma unroll
        for (int i = 0; i < 4; i++) {
            const int ob = (bg * 4 + i) * 32;
#pragma unroll
            for (int q = 0; q < 4; q++)
                red[w * 512 + ob + cg * 4 + q] = psum(acc[i][q]);
        }
        __syncthreads();

        float s0 = bu0, s1 = bu1;
#pragma unroll
        for (int ww = 0; ww < 8; ww++) {
            const float2 p = *(const float2*)&red[ww * 512 + o0];
            s0 += p.x;
            s1 += p.y;
        }

        const float h0 = tanhf(xwn.x + s0);
        const float h1 = tanhf(xwn.y + s1);
        out[nidx] = h0;
        out[nidx + 1] = h1;
        const int par1 = par ^ 1;
        g_h3[par1][c][b] = h0;
        g_h3[par1][c + 1][b] = h1;

        if (t == TT - 2) {   // h3(511) just produced -> out2, done
            const size_t o2 = (size_t)BB * TT * HH + (size_t)b * HH + c;
            out[o2] = h0;
            out[o2 + 1] = h1;
            break;
        }

        __threadfence();
        __syncthreads();   // also protects red[] reuse
        if (tid == 0) {
            const unsigned int target = (unsigned int)(t + 2);
            if (atomicAdd(&g_cnt, 1) == NB - 1) {
                g_cnt = 0;
                __threadfence();
                g_flag = target;
            } else {
                while (g_flag < target) { }
            }
        }
        __syncthreads();
    }
}

extern "C" void kernel_launch(void* const* d_in, const int* in_sizes, int n_in,
                              void* d_out, int out_size) {
    const float* x  = (const float*)d_in[0];
    const float* W  = (const float*)d_in[1];
    const float* bW = (const float*)d_in[2];
    const float* U  = (const float*)d_in[3];
    const float* bU = (const float*)d_in[4];
    float* out = (float*)d_out;

    const int smem_bytes = (32 * UPITCH + 8 * 512) * sizeof(float);
    cudaFuncSetAttribute(rnn_steps_kernel,
                         cudaFuncAttributeMaxDynamicSharedMemorySize, smem_bytes);

    dim3 ggrid(HH / 128, (BB * TT) / 128);  // (8, 256)
    gemm_xw_kernel<<<ggrid, 256>>>(x, W, bW, out);

    rnn_steps_kernel<<<NB, 256, smem_bytes>>>(U, bU, out);
}

// round 3
// speedup vs baseline: 1.1767x; 1.1216x over previous
#include <cuda_runtime.h>

#define TT 512
#define BB 64
#define II 1024
#define HH 1024
#define NB 128        // persistent CTAs (<=148 -> all resident, barrier safe)
#define UPITCH 1026   // padded smem pitch (floats)

// h3 exchange buffer, [parity][h-index][b]; b contiguous for coalesced staging
__device__ float g_h3[2][HH][BB];
__device__ unsigned int g_cnt;
__device__ volatile unsigned int g_flag;

__device__ __forceinline__ unsigned long long pk2(float lo, float hi) {
    unsigned long long r;
    asm("mov.b64 %0, {%1, %2};" : "=l"(r) : "f"(lo), "f"(hi));
    return r;
}
__device__ __forceinline__ unsigned long long ffma2(unsigned long long a,
                                                    unsigned long long b,
                                                    unsigned long long c) {
    unsigned long long d;
    asm("fma.rn.f32x2 %0, %1, %2, %3;" : "=l"(d) : "l"(a), "l"(b), "l"(c));
    return d;
}
__device__ __forceinline__ float psum(unsigned long long p) {
    float lo = __uint_as_float((unsigned int)(p & 0xFFFFFFFFull));
    float hi = __uint_as_float((unsigned int)(p >> 32));
    return lo + hi;
}
__device__ __forceinline__ void st_pair4(float* p, float4 v) {
    *(unsigned long long*)(p)     = pk2(v.x, v.y);
    *(unsigned long long*)(p + 2) = pk2(v.z, v.w);
}

// ---------------------------------------------------------------------------
// xw = x @ W^T + bW  (M=32768, N=1024, K=1024) -> d_out.  UNchanged control.
// Block (0,0) resets the grid-barrier state for the following kernel.
// ---------------------------------------------------------------------------
__global__ __launch_bounds__(256, 1)
void gemm_xw_kernel(const float* __restrict__ X, const float* __restrict__ W,
                    const float* __restrict__ bW, float* __restrict__ C) {
    if (blockIdx.x == 0 && blockIdx.y == 0 && threadIdx.x == 0) {
        g_cnt = 0;
        g_flag = 0;
    }

    __shared__ float xs[128][18];
    __shared__ float ws[128][18];

    const int tid = threadIdx.x;
    const int m0 = blockIdx.y * 128;
    const int n0 = blockIdx.x * 128;
    const int tm = tid & 15;
    const int tn = tid >> 4;
    const int lr = tid >> 2;
    const int lc = (tid & 3) << 2;

    const float* xg = X + (size_t)(m0 + lr) * II + lc;
    const float* wg = W + (size_t)(n0 + lr) * II + lc;

    unsigned long long acc[8][8];
#pragma unroll
    for (int i = 0; i < 8; i++)
#pragma unroll
        for (int j = 0; j < 8; j++) acc[i][j] = 0ull;

    float4 xa = *(const float4*)(xg);
    float4 xb = *(const float4*)(xg + 64 * II);
    float4 wa = *(const float4*)(wg);
    float4 wb = *(const float4*)(wg + 64 * II);

    for (int k0 = 0; k0 < II; k0 += 16) {
        __syncthreads();
        st_pair4(&xs[lr][lc], xa);
        st_pair4(&xs[lr + 64][lc], xb);
        st_pair4(&ws[lr][lc], wa);
        st_pair4(&ws[lr + 64][lc], wb);
        __syncthreads();
        if (k0 + 16 < II) {
            xa = *(const float4*)(xg + k0 + 16);
            xb = *(const float4*)(xg + 64 * II + k0 + 16);
            wa = *(const float4*)(wg + k0 + 16);
            wb = *(const float4*)(wg + 64 * II + k0 + 16);
        }
#pragma unroll
        for (int kp = 0; kp < 8; kp++) {
            unsigned long long af[8], bf[8];
#pragma unroll
            for (int i = 0; i < 8; i++)
                af[i] = *(const unsigned long long*)&xs[tm + 16 * i][kp * 2];
#pragma unroll
            for (int j = 0; j < 8; j++)
                bf[j] = *(const unsigned long long*)&ws[tn + 16 * j][kp * 2];
#pragma unroll
            for (int i = 0; i < 8; i++)
#pragma unroll
                for (int j = 0; j < 8; j++)
                    acc[i][j] = ffma2(af[i], bf[j], acc[i][j]);
        }
    }

#pragma unroll
    for (int i = 0; i < 8; i++) {
        const int m = m0 + tm + 16 * i;
#pragma unroll
        for (int j = 0; j < 8; j++) {
            const int n = n0 + tn + 16 * j;
            C[(size_t)m * HH + n] = psum(acc[i][j]) + bW[n];
        }
    }
}

// ---------------------------------------------------------------------------
// Persistent recurrence. 128 CTAs = 4(b) x 32(c) tiles of 16b x 32c.
// U slice (32 rows) resident in smem; h3(t) STAGED into smem each step via
// one coalesced 64KB burst, then compute is pure LDS.64 + FFMA2.
// ---------------------------------------------------------------------------
__global__ __launch_bounds__(256, 1)
void rnn_steps_kernel(const float* __restrict__ U, const float* __restrict__ bU,
                      float* __restrict__ out) {
    extern __shared__ float smem[];
    float* Usm = smem;                       // 32 * UPITCH  (~128.3 KB)
    float* Hsm = smem + 32 * UPITCH;         // 16 * UPITCH  (~64.2 KB)
    float* red = smem + 48 * UPITCH;         // 8 * 512      (16 KB)

    const int tid = threadIdx.x;
    const int cgid = blockIdx.x & 31;
    const int bgid = blockIdx.x >> 5;
    const int c0 = cgid * 32;
    const int b0 = bgid * 16;

    // load this CTA's 32 U rows (coalesced)
    for (int idx = tid; idx < 32 * 1024; idx += 256) {
        const int r = idx >> 10, k = idx & 1023;
        Usm[r * UPITCH + k] = U[(size_t)(c0 + r) * HH + k];
    }

    // this thread's 2 outputs within the tile
    const int o0 = 2 * tid;
    const int blo = o0 >> 5;
    const int clo = o0 & 31;
    const int b = b0 + blo;
    const int c = c0 + clo;
    const float bu0 = bU[c];
    const float bu1 = bU[c + 1];

    // split-k lane mapping: warp w owns k in [w*128, w*128+128)
    const int w = tid >> 5;
    const int lane = tid & 31;
    const int bg = lane & 3;            // b_local = i*4 + bg  (bank stride 2)
    const int cg = lane >> 2;           // c_local = q*8 + cg  (bank stride 2)
    const int kbase = w * 128;

    // staging mapping: task = it*256 + tid -> k = task>>2, quad g = task&3
    const int sg = tid & 3;
    const int sk = tid >> 2;            // + 64*it

    __syncthreads();

    // t = 0 : h3(0) = tanh(xw_0)
    {
        const size_t idx = ((size_t)b * TT) * HH + c;
        const float2 xw = *(const float2*)&out[idx];
        const float h0 = tanhf(xw.x);
        const float h1 = tanhf(xw.y);
        out[idx] = h0;
        out[idx + 1] = h1;
        g_h3[0][c][b] = h0;
        g_h3[0][c + 1][b] = h1;
    }
    __threadfence();
    __syncthreads();
    if (tid == 0) {
        if (atomicAdd(&g_cnt, 1) == NB - 1) {
            g_cnt = 0;
            __threadfence();
            g_flag = 1;
        } else {
            while (g_flag < 1u) { }
        }
    }
    __syncthreads();

    for (int t = 0; t < TT - 1; t++) {
        const int par = t & 1;

        // prefetch next xw (independent of everything below)
        const size_t nidx = ((size_t)b * TT + (t + 1)) * HH + c;
        const float2 xwn = *(const float2*)&out[nidx];

        // ---- stage h3(t) slice [b0..b0+15][:] into smem, transposed ----
        {
            const float* hb = &g_h3[par][0][0];
            float4 v[16];
#pragma unroll
            for (int it = 0; it < 16; it++) {
                const int k = sk + 64 * it;
                v[it] = __ldcg((const float4*)(hb + (size_t)k * BB + b0 + 4 * sg));
            }
#pragma unroll
            for (int it = 0; it < 16; it++) {
                const int k = sk + 64 * it;
                float* dst = Hsm + k;
                dst[(4 * sg + 0) * UPITCH] = v[it].x;
                dst[(4 * sg + 1) * UPITCH] = v[it].y;
                dst[(4 * sg + 2) * UPITCH] = v[it].z;
                dst[(4 * sg + 3) * UPITCH] = v[it].w;
            }
        }
        __syncthreads();

        // ---- tile GEMM from smem: pure LDS.64 + FFMA2 ----
        unsigned long long acc[4][4];
#pragma unroll
        for (int i = 0; i < 4; i++)
#pragma unroll
            for (int q = 0; q < 4; q++) acc[i][q] = 0ull;

#pragma unroll 8
        for (int kp = 0; kp < 64; kp++) {
            const int k0 = kbase + 2 * kp;
            unsigned long long a[4], u[4];
#pragma unroll
            for (int i = 0; i < 4; i++)
                a[i] = *(const unsigned long long*)&Hsm[(i * 4 + bg) * UPITCH + k0];
#pragma unroll
            for (int q = 0; q < 4; q++)
                u[q] = *(const unsigned long long*)&Usm[(q * 8 + cg) * UPITCH + k0];
#pragma unroll
            for (int i = 0; i < 4; i++)
#pragma unroll
                for (int q = 0; q < 4; q++)
                    acc[i][q] = ffma2(a[i], u[q], acc[i][q]);
        }

        // warp partials -> smem  (b_local = i*4+bg, c_local = q*8+cg)
#pragma unroll
        for (int i = 0; i < 4; i++) {
            const int ob = (i * 4 + bg) * 32;
#pragma unroll
            for (int q = 0; q < 4; q++)
                red[w * 512 + ob + q * 8 + cg] = psum(acc[i][q]);
        }
        __syncthreads();

        float s0 = bu0, s1 = bu1;
#pragma unroll
        for (int ww = 0; ww < 8; ww++) {
            const float2 p = *(const float2*)&red[ww * 512 + o0];
            s0 += p.x;
            s1 += p.y;
        }

        const float h0 = tanhf(xwn.x + s0);
        const float h1 = tanhf(xwn.y + s1);
        out[nidx] = h0;
        out[nidx + 1] = h1;
        const int par1 = par ^ 1;
        g_h3[par1][c][b] = h0;
        g_h3[par1][c + 1][b] = h1;

        if (t == TT - 2) {
            const size_t o2 = (size_t)BB * TT * HH + (size_t)b * HH + c;
            out[o2] = h0;
            out[o2 + 1] = h1;
            break;
        }

        __threadfence();
        __syncthreads();   // also protects red[]/Hsm reuse
        if (tid == 0) {
            const unsigned int target = (unsigned int)(t + 2);
            if (atomicAdd(&g_cnt, 1) == NB - 1) {
                g_cnt = 0;
                __threadfence();
                g_flag = target;
            } else {
                while (g_flag < target) { }
            }
        }
        __syncthreads();
    }
}

extern "C" void kernel_launch(void* const* d_in, const int* in_sizes, int n_in,
                              void* d_out, int out_size) {
    const float* x  = (const float*)d_in[0];
    const float* W  = (const float*)d_in[1];
    const float* bW = (const float*)d_in[2];
    const float* U  = (const float*)d_in[3];
    const float* bU = (const float*)d_in[4];
    float* out = (float*)d_out;

    const int smem_bytes = (48 * UPITCH + 8 * 512) * sizeof(float);
    cudaFuncSetAttribute(rnn_steps_kernel,
                         cudaFuncAttributeMaxDynamicSharedMemorySize, smem_bytes);

    dim3 ggrid(HH / 128, (BB * TT) / 128);  // (8, 256)
    gemm_xw_kernel<<<ggrid, 256>>>(x, W, bW, out);

    rnn_steps_kernel<<<NB, 256, smem_bytes>>>(U, bU, out);
}

// round 5
// speedup vs baseline: 1.1970x; 1.0172x over previous
#include <cuda_runtime.h>

#define TT 512
#define BB 64
#define II 1024
#define HH 1024
#define UPITCH 1026   // padded smem pitch (floats)

// h3 exchange buffer, [parity][h-index][b]; b contiguous for coalesced staging
__device__ float g_h3[2][HH][BB];
// row-scoped barrier state: 4 rows, padded to 128B apart
__device__ unsigned int g_cnt4[4 * 32];
__device__ volatile unsigned int g_flag4[4 * 32];

__device__ __forceinline__ unsigned long long pk2(float lo, float hi) {
    unsigned long long r;
    asm("mov.b64 %0, {%1, %2};" : "=l"(r) : "f"(lo), "f"(hi));
    return r;
}
__device__ __forceinline__ unsigned long long ffma2(unsigned long long a,
                                                    unsigned long long b,
                                                    unsigned long long c) {
    unsigned long long d;
    asm("fma.rn.f32x2 %0, %1, %2, %3;" : "=l"(d) : "l"(a), "l"(b), "l"(c));
    return d;
}
__device__ __forceinline__ float psum(unsigned long long p) {
    float lo = __uint_as_float((unsigned int)(p & 0xFFFFFFFFull));
    float hi = __uint_as_float((unsigned int)(p >> 32));
    return lo + hi;
}
__device__ __forceinline__ void st_pair4(float* p, float4 v) {
    *(unsigned long long*)(p)     = pk2(v.x, v.y);
    *(unsigned long long*)(p + 2) = pk2(v.z, v.w);
}

// ---------------------------------------------------------------------------
// xw = x @ W^T + bW  (M=32768, N=1024, K=1024) -> d_out.  (R3 version.)
// Block (0,0) resets the row-barrier state for the following kernel.
// ---------------------------------------------------------------------------
__global__ __launch_bounds__(256, 1)
void gemm_xw_kernel(const float* __restrict__ X, const float* __restrict__ W,
                    const float* __restrict__ bW, float* __restrict__ C) {
    if (blockIdx.x == 0 && blockIdx.y == 0 && threadIdx.x < 4) {
        g_cnt4[threadIdx.x * 32] = 0;
        g_flag4[threadIdx.x * 32] = 0;
    }

    __shared__ float xs[128][18];
    __shared__ float ws[128][18];

    const int tid = threadIdx.x;
    const int m0 = blockIdx.y * 128;
    const int n0 = blockIdx.x * 128;
    const int tm = tid & 15;
    const int tn = tid >> 4;
    const int lr = tid >> 2;
    const int lc = (tid & 3) << 2;

    const float* xg = X + (size_t)(m0 + lr) * II + lc;
    const float* wg = W + (size_t)(n0 + lr) * II + lc;

    unsigned long long acc[8][8];
#pragma unroll
    for (int i = 0; i < 8; i++)
#pragma unroll
        for (int j = 0; j < 8; j++) acc[i][j] = 0ull;

    float4 xa = *(const float4*)(xg);
    float4 xb = *(const float4*)(xg + 64 * II);
    float4 wa = *(const float4*)(wg);
    float4 wb = *(const float4*)(wg + 64 * II);

    for (int k0 = 0; k0 < II; k0 += 16) {
        __syncthreads();
        st_pair4(&xs[lr][lc], xa);
        st_pair4(&xs[lr + 64][lc], xb);
        st_pair4(&ws[lr][lc], wa);
        st_pair4(&ws[lr + 64][lc], wb);
        __syncthreads();
        if (k0 + 16 < II) {
            xa = *(const float4*)(xg + k0 + 16);
            xb = *(const float4*)(xg + 64 * II + k0 + 16);
            wa = *(const float4*)(wg + k0 + 16);
            wb = *(const float4*)(wg + 64 * II + k0 + 16);
        }
#pragma unroll
        for (int kp = 0; kp < 8; kp++) {
            unsigned long long af[8], bf[8];
#pragma unroll
            for (int i = 0; i < 8; i++)
                af[i] = *(const unsigned long long*)&xs[tm + 16 * i][kp * 2];
#pragma unroll
            for (int j = 0; j < 8; j++)
                bf[j] = *(const unsigned long long*)&ws[tn + 16 * j][kp * 2];
#pragma unroll
            for (int i = 0; i < 8; i++)
#pragma unroll
                for (int j = 0; j < 8; j++)
                    acc[i][j] = ffma2(af[i], bf[j], acc[i][j]);
        }
    }

#pragma unroll
    for (int i = 0; i < 8; i++) {
        const int m = m0 + tm + 16 * i;
#pragma unroll
        for (int j = 0; j < 8; j++) {
            const int n = n0 + tn + 16 * j;
            C[(size_t)m * HH + n] = psum(acc[i][j]) + bW[n];
        }
    }
}

// ---------------------------------------------------------------------------
// Persistent recurrence. 128 CTAs = 4(b) x 32(c) tiles of 16b x 32c.
// Row-scoped barriers (32 CTAs sharing bgid). Warp w owns k-strips {w, w+8}
// (64 k each); staging of half1 (k>=512) overlaps with pass1 compute.
// ---------------------------------------------------------------------------
__global__ __launch_bounds__(256, 1)
void rnn_steps_kernel(const float* __restrict__ U, const float* __restrict__ bU,
                      float* __restrict__ out) {
    extern __shared__ float fsmem[];
    float* Usm = fsmem;                  // 32 * UPITCH
    float* Hsm = fsmem + 32 * UPITCH;    // 16 * UPITCH
    float* red = fsmem + 48 * UPITCH;    // 8 * 512

    const int tid = threadIdx.x;
    const int cgid = blockIdx.x & 31;
    const int bgid = blockIdx.x >> 5;
    const int c0 = cgid * 32;
    const int b0 = bgid * 16;
    const int bslot = bgid * 32;

    for (int idx = tid; idx < 32 * 1024; idx += 256) {
        const int r = idx >> 10, k = idx & 1023;
        Usm[r * UPITCH + k] = U[(size_t)(c0 + r) * HH + k];
    }

    const int o0 = 2 * tid;
    const int blo = o0 >> 5;
    const int clo = o0 & 31;
    const int b = b0 + blo;
    const int c = c0 + clo;
    const float bu0 = bU[c];
    const float bu1 = bU[c + 1];

    const int w = tid >> 5;
    const int lane = tid & 31;
    const int bg = lane & 3;
    const int cg = lane >> 2;
    const int kb1 = w * 64;          // pass1 strip base (k < 512)
    const int kb2 = 512 + w * 64;    // pass2 strip base (k >= 512)

    const int sg = tid & 3;
    const int sk = tid >> 2;         // + 64*it

    __syncthreads();

    // t = 0 : h3(0) = tanh(xw_0)
    {
        const size_t idx = ((size_t)b * TT) * HH + c;
        const float2 xw = *(const float2*)&out[idx];
        const float h0 = tanhf(xw.x);
        const float h1 = tanhf(xw.y);
        out[idx] = h0;
        out[idx + 1] = h1;
        g_h3[0][c][b] = h0;
        g_h3[0][c + 1][b] = h1;
    }
    __threadfence();
    __syncthreads();
    if (tid == 0) {
        if (atomicAdd(&g_cnt4[bslot], 1) == 31) {
            g_cnt4[bslot] = 0;
            __threadfence();
            g_flag4[bslot] = 1;
        } else {
            while (g_flag4[bslot] < 1u) { }
        }
    }
    __syncthreads();

    for (int t = 0; t < TT - 1; t++) {
        const int par = t & 1;
        const size_t nidx = ((size_t)b * TT + (t + 1)) * HH + c;
        const float2 xwn = *(const float2*)&out[nidx];
        const float* hb = &g_h3[par][0][0];

        // ---- stage half0 (k < 512) ----
        {
            float4 v[8];
#pragma unroll
            for (int it = 0; it < 8; it++) {
                const int k = sk + 64 * it;
                v[it] = __ldcg((const float4*)(hb + (size_t)k * BB + b0 + 4 * sg));
            }
#pragma unroll
            for (int it = 0; it < 8; it++) {
                const int k = sk + 64 * it;
                float* dst = Hsm + k;
                dst[(4 * sg + 0) * UPITCH] = v[it].x;
                dst[(4 * sg + 1) * UPITCH] = v[it].y;
                dst[(4 * sg + 2) * UPITCH] = v[it].z;
                dst[(4 * sg + 3) * UPITCH] = v[it].w;
            }
        }
        __syncthreads();

        // ---- issue half1 LDGs (k >= 512), latency hidden under pass1 ----
        float4 v1[8];
#pragma unroll
        for (int it = 0; it < 8; it++) {
            const int k = 512 + sk + 64 * it;
            v1[it] = __ldcg((const float4*)(hb + (size_t)k * BB + b0 + 4 * sg));
        }

        unsigned long long acc[4][4];
#pragma unroll
        for (int i = 0; i < 4; i++)
#pragma unroll
            for (int q = 0; q < 4; q++) acc[i][q] = 0ull;

        // ---- pass1: strip w (k in [kb1, kb1+64)) ----
#pragma unroll 8
        for (int kp = 0; kp < 32; kp++) {
            const int k0 = kb1 + 2 * kp;
            unsigned long long a[4], u[4];
#pragma unroll
            for (int i = 0; i < 4; i++)
                a[i] = *(const unsigned long long*)&Hsm[(i * 4 + bg) * UPITCH + k0];
#pragma unroll
            for (int q = 0; q < 4; q++)
                u[q] = *(const unsigned long long*)&Usm[(q * 8 + cg) * UPITCH + k0];
#pragma unroll
            for (int i = 0; i < 4; i++)
#pragma unroll
                for (int q = 0; q < 4; q++)
                    acc[i][q] = ffma2(a[i], u[q], acc[i][q]);
        }

        // ---- store half1 to smem ----
#pragma unroll
        for (int it = 0; it < 8; it++) {
            const int k = 512 + sk + 64 * it;
            float* dst = Hsm + k;
            dst[(4 * sg + 0) * UPITCH] = v1[it].x;
            dst[(4 * sg + 1) * UPITCH] = v1[it].y;
            dst[(4 * sg + 2) * UPITCH] = v1[it].z;
            dst[(4 * sg + 3) * UPITCH] = v1[it].w;
        }
        __syncthreads();

        // ---- pass2: strip w+8 (k in [kb2, kb2+64)) ----
#pragma unroll 8
        for (int kp = 0; kp < 32; kp++) {
            const int k0 = kb2 + 2 * kp;
            unsigned long long a[4], u[4];
#pragma unroll
            for (int i = 0; i < 4; i++)
                a[i] = *(const unsigned long long*)&Hsm[(i * 4 + bg) * UPITCH + k0];
#pragma unroll
            for (int q = 0; q < 4; q++)
                u[q] = *(const unsigned long long*)&Usm[(q * 8 + cg) * UPITCH + k0];
#pragma unroll
            for (int i = 0; i < 4; i++)
#pragma unroll
                for (int q = 0; q < 4; q++)
                    acc[i][q] = ffma2(a[i], u[q], acc[i][q]);
        }

        // ---- cross-warp reduction ----
#pragma unroll
        for (int i = 0; i < 4; i++) {
            const int ob = (i * 4 + bg) * 32;
#pragma unroll
            for (int q = 0; q < 4; q++)
                red[w * 512 + ob + q * 8 + cg] = psum(acc[i][q]);
        }
        __syncthreads();

        float s0 = bu0, s1 = bu1;
#pragma unroll
        for (int ww = 0; ww < 8; ww++) {
            const float2 p = *(const float2*)&red[ww * 512 + o0];
            s0 += p.x;
            s1 += p.y;
        }

        const float h0 = tanhf(xwn.x + s0);
        const float h1 = tanhf(xwn.y + s1);
        out[nidx] = h0;
        out[nidx + 1] = h1;
        const int par1 = par ^ 1;
        g_h3[par1][c][b] = h0;
        g_h3[par1][c + 1][b] = h1;

        if (t == TT - 2) {
            const size_t o2 = (size_t)BB * TT * HH + (size_t)b * HH + c;
            out[o2] = h0;
            out[o2 + 1] = h1;
            break;
        }

        __threadfence();
        __syncthreads();   // also protects red[]/Hsm reuse
        if (tid == 0) {
            const unsigned int target = (unsigned int)(t + 2);
            if (atomicAdd(&g_cnt4[bslot], 1) == 31) {
                g_cnt4[bslot] = 0;
                __threadfence();
                g_flag4[bslot] = target;
            } else {
                while (g_flag4[bslot] < target) { }
            }
        }
        __syncthreads();
    }
}

extern "C" void kernel_launch(void* const* d_in, const int* in_sizes, int n_in,
                              void* d_out, int out_size) {
    const float* x  = (const float*)d_in[0];
    const float* W  = (const float*)d_in[1];
    const float* bW = (const float*)d_in[2];
    const float* U  = (const float*)d_in[3];
    const float* bU = (const float*)d_in[4];
    float* out = (float*)d_out;

    const int rnn_smem = (48 * UPITCH + 8 * 512) * sizeof(float);
    cudaFuncSetAttribute(rnn_steps_kernel,
                         cudaFuncAttributeMaxDynamicSharedMemorySize, rnn_smem);

    dim3 ggrid(HH / 128, (BB * TT) / 128);  // (8, 256)
    gemm_xw_kernel<<<ggrid, 256>>>(x, W, bW, out);

    rnn_steps_kernel<<<128, 256, rnn_smem>>>(U, bU, out);
}